// round 1
// baseline (speedup 1.0000x reference)
#include <cuda_runtime.h>
#include <math.h>

#define Nn 50000
#define Ee 400000
#define Hh 128
#define Gg 512
#define COUT 10

static constexpr float EPSBN = 1e-5f;
static constexpr float BNB   = 1e-4f;

// ---------------- scratch (static device allocations) ----------------
__device__ float g_h[Nn*Hh];
__device__ float g_t[Nn*Hh];
__device__ float g_s[Nn*Hh];
__device__ float g_stats[512];
__device__ float g_mean[256];
__device__ float g_rstd[256];
__device__ float g_disU[Nn];
__device__ float g_dis0[Nn];
__device__ float g_dis1[Nn];
__device__ float g_epro[Nn*4];
__device__ float g_t2[Nn*2];
__device__ float g_nraw[Nn*2];
__device__ float g_natt[Nn*2];
__device__ float g_eatt[Ee*2];
__device__ int   g_gstart[Gg+1];
__device__ float g_cat[Gg*256];
__device__ float g_hd[Gg*128];
__device__ float g_logits[Gg*COUT];

// ---------------- small utility kernels ----------------
__global__ void fill_f32(float* p, float v, int n) {
    int i = blockIdx.x*blockDim.x + threadIdx.x;
    if (i < n) p[i] = v;
}

__global__ void count_deg(const int* __restrict__ src, float* deg, int E) {
    int i = blockIdx.x*blockDim.x + threadIdx.x;
    if (i < E) atomicAdd(&deg[src[i]], 1.0f);
}

__global__ void rsqrt_inplace(float* p, int n) {
    int i = blockIdx.x*blockDim.x + threadIdx.x;
    if (i < n) p[i] = rsqrtf(p[i]);
}

__global__ void gstart_kernel(const int* __restrict__ batch, int* gstart, int n, int G) {
    int i = blockIdx.x*blockDim.x + threadIdx.x;
    if (i >= n) return;
    int b  = batch[i];
    int pb = (i == 0) ? -1 : batch[i-1];
    for (int g = pb+1; g <= b; g++) gstart[g] = i;
    if (i == n-1) {
        for (int g = b+1; g <= G; g++) gstart[g] = n;
    }
}

// column sums & sumsq. stride (grid*block) is a multiple of C -> column fixed per thread.
template<int C>
__global__ void colstats(const float* __restrict__ A, int lda, int aoff,
                         const float* __restrict__ rs, int rss, int rso,
                         int n, float* sums) {
    long total  = (long)n * C;
    long stride = (long)gridDim.x * blockDim.x;
    long i0     = (long)blockIdx.x*blockDim.x + threadIdx.x;
    if (i0 >= total) return;
    int c = (int)(i0 % C);
    float s0 = 0.f, s1 = 0.f;
    for (long i = i0; i < total; i += stride) {
        int r = (int)(i / C);
        float v = A[(long)r*lda + aoff + c];
        if (rs) v *= rs[r*rss + rso];
        s0 += v; s1 += v*v;
    }
    atomicAdd(&sums[c], s0);
    atomicAdd(&sums[C+c], s1);
}

__global__ void finalize_stats(const float* __restrict__ sums, int C, float inv_n,
                               float* mean, float* rstd) {
    int c = threadIdx.x + blockIdx.x*blockDim.x;
    if (c < C) {
        float m = sums[c]*inv_n;
        float var = sums[C+c]*inv_n - m*m;
        mean[c] = m;
        rstd[c] = rsqrtf(var + EPSBN);
    }
}

// ---------------- big GEMM: out[n,128] = act( BN(rs*A)[n,128] @ W[128,128] ) ----------------
// 64 rows x 128 cols per block, 256 threads, 8x4 per thread. W + A tile in shared.
static constexpr int GEMM_SMEM = (64*128 + 128*128) * 4;

__global__ __launch_bounds__(256) void gemm128(
    const float* __restrict__ A,
    const float* __restrict__ rs, int rss, int rso,
    const float* __restrict__ mean, const float* __restrict__ rstd,
    const float* __restrict__ W, float* __restrict__ out, int n, int act) {
    extern __shared__ float sm[];
    float*  As  = sm;                       // 64*128
    float4* Ws4 = (float4*)(sm + 64*128);   // 128*32 float4
    int tid  = threadIdx.x;
    int row0 = blockIdx.x * 64;

    const float4* Wg = (const float4*)W;
    #pragma unroll 4
    for (int i = tid; i < 128*32; i += 256) Ws4[i] = Wg[i];

    for (int i = tid; i < 64*128; i += 256) {
        int r = i >> 7, c = i & 127;
        int gr = row0 + r;
        float v = 0.f;
        if (gr < n) {
            v = A[gr*128 + c];
            if (rs) v *= rs[gr*rss + rso];
            v = (v - mean[c]) * rstd[c] + BNB;
        }
        As[i] = v;
    }
    __syncthreads();

    int tc = tid & 31, tr = tid >> 5;
    float acc[8][4];
    #pragma unroll
    for (int i = 0; i < 8; i++)
        #pragma unroll
        for (int j = 0; j < 4; j++) acc[i][j] = 0.f;

    for (int k = 0; k < 128; k++) {
        float4 w = Ws4[k*32 + tc];
        #pragma unroll
        for (int i = 0; i < 8; i++) {
            float a = As[(tr*8 + i)*128 + k];
            acc[i][0] += a*w.x; acc[i][1] += a*w.y;
            acc[i][2] += a*w.z; acc[i][3] += a*w.w;
        }
    }

    float4* O4 = (float4*)out;
    #pragma unroll
    for (int i = 0; i < 8; i++) {
        int gr = row0 + tr*8 + i;
        if (gr < n) {
            float4 o;
            o.x = acc[i][0]; o.y = acc[i][1]; o.z = acc[i][2]; o.w = acc[i][3];
            if (act == 1) {
                o.x = fmaxf(o.x, 0.f); o.y = fmaxf(o.y, 0.f);
                o.z = fmaxf(o.z, 0.f); o.w = fmaxf(o.w, 0.f);
            }
            O4[gr*32 + tc] = o;
        }
    }
}

// ---------------- scatter kernels ----------------
// s[v] = t[v] * dis[v]^2   (self-loop term)
__global__ void loop_init(const float* __restrict__ t, const float* __restrict__ dis,
                          float* __restrict__ s, int n) {
    int i = blockIdx.x*blockDim.x + threadIdx.x;
    if (i >= n*32) return;
    int v = i >> 5;
    float d = dis[v]; d *= d;
    float4 x = ((const float4*)t)[i];
    float4 o; o.x = x.x*d; o.y = x.y*d; o.z = x.z*d; o.w = x.w*d;
    ((float4*)s)[i] = o;
}

// one warp per edge: s[dst] += dis[src]*ew*dis[dst] * t[src]
__global__ __launch_bounds__(256) void scatter128(
    const float* __restrict__ t, const int* __restrict__ src, const int* __restrict__ dst,
    const float* __restrict__ dis, const float* __restrict__ ew, int ewo,
    float* __restrict__ s_out, int E) {
    int gtid = blockIdx.x*blockDim.x + threadIdx.x;
    int e = gtid >> 5, lane = gtid & 31;
    if (e >= E) return;
    int sv = src[e], dv = dst[e];
    float w = dis[sv]*dis[dv];
    if (ew) w *= ew[e*2 + ewo];
    float4 v = ((const float4*)t)[sv*32 + lane];
    float* o = s_out + dv*128 + lane*4;
    atomicAdd(o+0, w*v.x); atomicAdd(o+1, w*v.y);
    atomicAdd(o+2, w*v.z); atomicAdd(o+3, w*v.w);
}

__global__ void bias_relu(const float* __restrict__ s, const float* __restrict__ b,
                          float* __restrict__ h, int n) {
    int i = blockIdx.x*blockDim.x + threadIdx.x;
    if (i >= n*32) return;
    float4 x = ((const float4*)s)[i];
    float4 bb = ((const float4*)b)[i & 31];
    float4 o;
    o.x = fmaxf(x.x + bb.x, 0.f); o.y = fmaxf(x.y + bb.y, 0.f);
    o.z = fmaxf(x.z + bb.z, 0.f); o.w = fmaxf(x.w + bb.w, 0.f);
    ((float4*)h)[i] = o;
}

// ---------------- attention ----------------
// per node: 4 edge projections (eW) + 2 node-att projections (naW)
__global__ void proj_kernel(const float* __restrict__ h, const float* __restrict__ eW,
                            const float* __restrict__ naW, float* __restrict__ epro,
                            float* __restrict__ t2, int n) {
    __shared__ float sEW[512];
    __shared__ float sNA[256];
    int tid = threadIdx.x;
    for (int i = tid; i < 512; i += blockDim.x) sEW[i] = eW[i];
    for (int i = tid; i < 256; i += blockDim.x) sNA[i] = naW[i];
    __syncthreads();
    int lane = tid & 31;
    int w0 = (blockIdx.x*blockDim.x + tid) >> 5;
    int nw = (gridDim.x*blockDim.x) >> 5;
    for (int v = w0; v < n; v += nw) {
        float4 hv = ((const float4*)h)[v*32 + lane];
        float hx[4] = {hv.x, hv.y, hv.z, hv.w};
        float p0=0,p1=0,q0=0,q1=0,u0=0,u1=0;
        #pragma unroll
        for (int i = 0; i < 4; i++) {
            int k = lane*4 + i; float x = hx[i];
            p0 += x*sEW[k*2+0];        p1 += x*sEW[k*2+1];
            q0 += x*sEW[(128+k)*2+0];  q1 += x*sEW[(128+k)*2+1];
            u0 += x*sNA[k*2+0];        u1 += x*sNA[k*2+1];
        }
        #pragma unroll
        for (int o = 16; o; o >>= 1) {
            p0 += __shfl_xor_sync(0xffffffffu, p0, o);
            p1 += __shfl_xor_sync(0xffffffffu, p1, o);
            q0 += __shfl_xor_sync(0xffffffffu, q0, o);
            q1 += __shfl_xor_sync(0xffffffffu, q1, o);
            u0 += __shfl_xor_sync(0xffffffffu, u0, o);
            u1 += __shfl_xor_sync(0xffffffffu, u1, o);
        }
        if (lane == 0) {
            epro[v*4+0]=p0; epro[v*4+1]=p1; epro[v*4+2]=q0; epro[v*4+3]=q1;
            t2[v*2+0]=u0; t2[v*2+1]=u1;
        }
    }
}

__global__ void edge_att_kernel(const int* __restrict__ src, const int* __restrict__ dst,
                                const float* __restrict__ epro, const float* __restrict__ eb,
                                float* __restrict__ eatt, float* deg0, float* deg1, int E) {
    int e = blockIdx.x*blockDim.x + threadIdx.x;
    if (e >= E) return;
    int s = src[e], d = dst[e];
    float l0 = epro[s*4+0] + epro[d*4+2] + eb[0];
    float l1 = epro[s*4+1] + epro[d*4+3] + eb[1];
    float m = fmaxf(l0, l1);
    float e0 = expf(l0 - m), e1 = expf(l1 - m);
    float inv = 1.f/(e0+e1);
    float a0 = e0*inv, a1 = e1*inv;
    eatt[e*2+0] = a0; eatt[e*2+1] = a1;
    atomicAdd(&deg0[s], a0);
    atomicAdd(&deg1[s], a1);
}

__global__ void natt_init(const float* __restrict__ t2, const float* __restrict__ disU,
                          float* __restrict__ nraw, int n) {
    int v = blockIdx.x*blockDim.x + threadIdx.x;
    if (v >= n) return;
    float d = disU[v]; d *= d;
    nraw[v*2+0] = t2[v*2+0]*d;
    nraw[v*2+1] = t2[v*2+1]*d;
}

__global__ void scatter2(const int* __restrict__ src, const int* __restrict__ dst,
                         const float* __restrict__ disU, const float* __restrict__ t2,
                         float* __restrict__ nraw, int E) {
    int e = blockIdx.x*blockDim.x + threadIdx.x;
    if (e >= E) return;
    int s = src[e], d = dst[e];
    float c = disU[s]*disU[d];
    atomicAdd(&nraw[d*2+0], c*t2[s*2+0]);
    atomicAdd(&nraw[d*2+1], c*t2[s*2+1]);
}

__global__ void natt_fin(const float* __restrict__ nraw, const float* __restrict__ nab,
                         float* __restrict__ natt, int n) {
    int v = blockIdx.x*blockDim.x + threadIdx.x;
    if (v >= n) return;
    float l0 = nraw[v*2+0] + nab[0];
    float l1 = nraw[v*2+1] + nab[1];
    float m = fmaxf(l0, l1);
    float e0 = expf(l0 - m), e1 = expf(l1 - m);
    float inv = 1.f/(e0+e1);
    natt[v*2+0] = e0*inv; natt[v*2+1] = e1*inv;
}

// pool with fused bias + elu: cat[g, off+c] = sum_{v in group g} elu(s[v,c] + b[c])
__global__ void pool_elu(const float* __restrict__ s, const float* __restrict__ b,
                         const int* __restrict__ gstart, float* __restrict__ cat, int off) {
    int g = blockIdx.x, c = threadIdx.x;
    int st = gstart[g], en = gstart[g+1];
    float bc = b[c], acc = 0.f;
    for (int v = st; v < en; v++) {
        float z = s[v*128 + c] + bc;
        acc += (z > 0.f) ? z : expm1f(z);
    }
    cat[g*256 + off + c] = acc;
}

// ---------------- head GEMM: one block per row ----------------
__global__ void head_gemm(const float* __restrict__ A, int lda, int aoff,
                          const float* __restrict__ mean, const float* __restrict__ rstd,
                          const float* __restrict__ W, const float* __restrict__ b,
                          float* __restrict__ out, int K, int cols, int act) {
    __shared__ float a[256];
    int r = blockIdx.x;
    for (int k = threadIdx.x; k < K; k += blockDim.x)
        a[k] = (A[r*lda + aoff + k] - mean[k]) * rstd[k] + BNB;
    __syncthreads();
    for (int c = threadIdx.x; c < cols; c += blockDim.x) {
        float acc = b[c];
        for (int k = 0; k < K; k++) acc += a[k] * W[k*cols + c];
        if (act == 1) acc = fmaxf(acc, 0.f);
        else if (act == 2) {
            acc = (acc > 0.f) ? acc : expm1f(acc);
            acc = (acc > 0.f) ? acc : expm1f(acc);
        }
        out[r*cols + c] = acc;
    }
}

__global__ void log_softmax10(const float* __restrict__ in, float* __restrict__ out, int G) {
    int r = blockIdx.x*blockDim.x + threadIdx.x;
    if (r >= G) return;
    float v[COUT]; float m = -1e30f;
    #pragma unroll
    for (int i = 0; i < COUT; i++) { v[i] = in[r*COUT + i]; m = fmaxf(m, v[i]); }
    float s = 0.f;
    #pragma unroll
    for (int i = 0; i < COUT; i++) s += expf(v[i] - m);
    float lse = m + logf(s);
    #pragma unroll
    for (int i = 0; i < COUT; i++) out[r*COUT + i] = v[i] - lse;
}

// ---------------- host orchestration ----------------
extern "C" void kernel_launch(void* const* d_in, const int* in_sizes, int n_in,
                              void* d_out, int out_size) {
    const float* x      = (const float*)d_in[0];
    const float* W_feat = (const float*)d_in[1];
    const float* conv_Ws= (const float*)d_in[2];
    const float* conv_bs= (const float*)d_in[3];
    const float* eW     = (const float*)d_in[4];
    const float* eb     = (const float*)d_in[5];
    const float* naW    = (const float*)d_in[6];
    const float* nab    = (const float*)d_in[7];
    const float* xcW    = (const float*)d_in[8];
    const float* xcb    = (const float*)d_in[9];
    const float* xoW    = (const float*)d_in[10];
    const float* xob    = (const float*)d_in[11];
    const float* cW1    = (const float*)d_in[12];
    const float* cb1    = (const float*)d_in[13];
    const float* cW2    = (const float*)d_in[14];
    const float* cb2    = (const float*)d_in[15];
    const float* oW1    = (const float*)d_in[16];
    const float* ob1    = (const float*)d_in[17];
    const float* oW2    = (const float*)d_in[18];
    const float* ob2    = (const float*)d_in[19];
    const float* coW1   = (const float*)d_in[20];
    const float* cob1   = (const float*)d_in[21];
    const float* coW2   = (const float*)d_in[22];
    const float* cob2   = (const float*)d_in[23];
    const int* esrc     = (const int*)d_in[24];
    const int* edst     = (const int*)d_in[25];
    const int* batch    = (const int*)d_in[26];
    float* out = (float*)d_out;

    float *p_h,*p_t,*p_s,*p_stats,*p_mean,*p_rstd,*p_disU,*p_dis0,*p_dis1;
    float *p_epro,*p_t2,*p_nraw,*p_natt,*p_eatt,*p_cat,*p_hd,*p_logits;
    int* p_gstart;
    cudaGetSymbolAddress((void**)&p_h, g_h);
    cudaGetSymbolAddress((void**)&p_t, g_t);
    cudaGetSymbolAddress((void**)&p_s, g_s);
    cudaGetSymbolAddress((void**)&p_stats, g_stats);
    cudaGetSymbolAddress((void**)&p_mean, g_mean);
    cudaGetSymbolAddress((void**)&p_rstd, g_rstd);
    cudaGetSymbolAddress((void**)&p_disU, g_disU);
    cudaGetSymbolAddress((void**)&p_dis0, g_dis0);
    cudaGetSymbolAddress((void**)&p_dis1, g_dis1);
    cudaGetSymbolAddress((void**)&p_epro, g_epro);
    cudaGetSymbolAddress((void**)&p_t2, g_t2);
    cudaGetSymbolAddress((void**)&p_nraw, g_nraw);
    cudaGetSymbolAddress((void**)&p_natt, g_natt);
    cudaGetSymbolAddress((void**)&p_eatt, g_eatt);
    cudaGetSymbolAddress((void**)&p_cat, g_cat);
    cudaGetSymbolAddress((void**)&p_hd, g_hd);
    cudaGetSymbolAddress((void**)&p_logits, g_logits);
    cudaGetSymbolAddress((void**)&p_gstart, g_gstart);

    cudaFuncSetAttribute(gemm128, cudaFuncAttributeMaxDynamicSharedMemorySize, GEMM_SMEM);

    const int N = Nn, E = Ee, G = Gg;
    const int NB = (N + 63) / 64;
    const int NT = (N + 255) / 256;
    const int ET = (E + 255) / 256;
    const int NV = (N*32 + 255) / 256;
    const int SCAT = (E*32) / 256;

    // degrees (unit) + group starts
    fill_f32<<<NT,256>>>(p_disU, 1.f, N);
    fill_f32<<<NT,256>>>(p_dis0, 1.f, N);
    fill_f32<<<NT,256>>>(p_dis1, 1.f, N);
    count_deg<<<ET,256>>>(esrc, p_disU, E);
    rsqrt_inplace<<<NT,256>>>(p_disU, N);
    gstart_kernel<<<NT,256>>>(batch, p_gstart, N, G);

    // h = relu(BN(x) @ W_feat)
    cudaMemsetAsync(p_stats, 0, 2048);
    colstats<128><<<512,256>>>(x, 128, 0, nullptr, 0, 0, N, p_stats);
    finalize_stats<<<1,256>>>(p_stats, 128, 1.f/N, p_mean, p_rstd);
    gemm128<<<NB,256,GEMM_SMEM>>>(x, nullptr,0,0, p_mean, p_rstd, W_feat, p_h, N, 1);

    // 3 GCN layers
    for (int l = 0; l < 3; l++) {
        cudaMemsetAsync(p_stats, 0, 2048);
        colstats<128><<<512,256>>>(p_h, 128, 0, nullptr, 0, 0, N, p_stats);
        finalize_stats<<<1,256>>>(p_stats, 128, 1.f/N, p_mean, p_rstd);
        gemm128<<<NB,256,GEMM_SMEM>>>(p_h, nullptr,0,0, p_mean, p_rstd,
                                      conv_Ws + l*128*128, p_t, N, 0);
        loop_init<<<NV,256>>>(p_t, p_disU, p_s, N);
        scatter128<<<SCAT,256>>>(p_t, esrc, edst, p_disU, nullptr, 0, p_s, E);
        bias_relu<<<NV,256>>>(p_s, conv_bs + l*128, p_h, N);
    }

    // attention projections + edge/node attention
    proj_kernel<<<512,256>>>(p_h, eW, naW, p_epro, p_t2, N);
    edge_att_kernel<<<ET,256>>>(esrc, edst, p_epro, eb, p_eatt, p_dis0, p_dis1, E);
    rsqrt_inplace<<<NT,256>>>(p_dis0, N);
    rsqrt_inplace<<<NT,256>>>(p_dis1, N);
    natt_init<<<NT,256>>>(p_t2, p_disU, p_nraw, N);
    scatter2<<<ET,256>>>(esrc, edst, p_disU, p_t2, p_nraw, E);
    natt_fin<<<NT,256>>>(p_nraw, nab, p_natt, N);

    // XC branch
    cudaMemsetAsync(p_stats, 0, 2048);
    colstats<128><<<512,256>>>(p_h, 128, 0, p_natt, 2, 0, N, p_stats);
    finalize_stats<<<1,256>>>(p_stats, 128, 1.f/N, p_mean, p_rstd);
    gemm128<<<NB,256,GEMM_SMEM>>>(p_h, p_natt, 2, 0, p_mean, p_rstd, xcW, p_t, N, 0);
    loop_init<<<NV,256>>>(p_t, p_dis0, p_s, N);
    scatter128<<<SCAT,256>>>(p_t, esrc, edst, p_dis0, p_eatt, 0, p_s, E);
    pool_elu<<<G,128>>>(p_s, xcb, p_gstart, p_cat, 0);

    // XO branch
    cudaMemsetAsync(p_stats, 0, 2048);
    colstats<128><<<512,256>>>(p_h, 128, 0, p_natt, 2, 1, N, p_stats);
    finalize_stats<<<1,256>>>(p_stats, 128, 1.f/N, p_mean, p_rstd);
    gemm128<<<NB,256,GEMM_SMEM>>>(p_h, p_natt, 2, 1, p_mean, p_rstd, xoW, p_t, N, 0);
    loop_init<<<NV,256>>>(p_t, p_dis1, p_s, N);
    scatter128<<<SCAT,256>>>(p_t, esrc, edst, p_dis1, p_eatt, 1, p_s, E);
    pool_elu<<<G,128>>>(p_s, xob, p_gstart, p_cat, 128);

    // ---- C head ----
    cudaMemsetAsync(p_stats, 0, 2048);
    colstats<128><<<64,256>>>(p_cat, 256, 0, nullptr, 0, 0, G, p_stats);
    finalize_stats<<<1,256>>>(p_stats, 128, 1.f/G, p_mean, p_rstd);
    head_gemm<<<G,128>>>(p_cat, 256, 0, p_mean, p_rstd, cW1, cb1, p_hd, 128, 128, 1);
    cudaMemsetAsync(p_stats, 0, 2048);
    colstats<128><<<64,256>>>(p_hd, 128, 0, nullptr, 0, 0, G, p_stats);
    finalize_stats<<<1,256>>>(p_stats, 128, 1.f/G, p_mean, p_rstd);
    head_gemm<<<G,128>>>(p_hd, 128, 0, p_mean, p_rstd, cW2, cb2, p_logits, 128, COUT, 0);
    log_softmax10<<<(G+127)/128,128>>>(p_logits, out, G);

    // ---- O head ----
    cudaMemsetAsync(p_stats, 0, 2048);
    colstats<128><<<64,256>>>(p_cat, 256, 128, nullptr, 0, 0, G, p_stats);
    finalize_stats<<<1,256>>>(p_stats, 128, 1.f/G, p_mean, p_rstd);
    head_gemm<<<G,128>>>(p_cat, 256, 128, p_mean, p_rstd, oW1, ob1, p_hd, 128, 128, 1);
    cudaMemsetAsync(p_stats, 0, 2048);
    colstats<128><<<64,256>>>(p_hd, 128, 0, nullptr, 0, 0, G, p_stats);
    finalize_stats<<<1,256>>>(p_stats, 128, 1.f/G, p_mean, p_rstd);
    head_gemm<<<G,128>>>(p_hd, 128, 0, p_mean, p_rstd, oW2, ob2, p_logits, 128, COUT, 0);
    log_softmax10<<<(G+127)/128,128>>>(p_logits, out + G*COUT, G);

    // ---- CO head ----
    cudaMemsetAsync(p_stats, 0, 2048);
    colstats<256><<<64,256>>>(p_cat, 256, 0, nullptr, 0, 0, G, p_stats);
    finalize_stats<<<1,256>>>(p_stats, 256, 1.f/G, p_mean, p_rstd);
    head_gemm<<<G,128>>>(p_cat, 256, 0, p_mean, p_rstd, coW1, cob1, p_hd, 256, 128, 2);
    cudaMemsetAsync(p_stats, 0, 2048);
    colstats<128><<<64,256>>>(p_hd, 128, 0, nullptr, 0, 0, G, p_stats);
    finalize_stats<<<1,256>>>(p_stats, 128, 1.f/G, p_mean, p_rstd);
    head_gemm<<<G,128>>>(p_hd, 128, 0, p_mean, p_rstd, coW2, cob2, p_logits, 128, COUT, 0);
    log_softmax10<<<(G+127)/128,128>>>(p_logits, out + 2*G*COUT, G);
}

// round 2
// speedup vs baseline: 1.2948x; 1.2948x over previous
#include <cuda_runtime.h>
#include <math.h>

#define Nn 50000
#define Ee 400000
#define Hh 128
#define Gg 512
#define COUT 10

static constexpr float EPSBN = 1e-5f;
static constexpr float BNB   = 1e-4f;

// ---------------- scratch (static device allocations) ----------------
__device__ float g_h[Nn*Hh];
__device__ float g_t[Nn*Hh];
__device__ float g_s[Nn*Hh];
__device__ float g_stats[512];
__device__ float g_mean[256];
__device__ float g_rstd[256];
__device__ float g_disU[Nn];
__device__ float g_dis0[Nn];
__device__ float g_dis1[Nn];
__device__ float g_epro[Nn*4];
__device__ float g_t2[Nn*2];
__device__ float g_nraw[Nn*2];
__device__ float g_natt[Nn*2];
__device__ float g_eatt[Ee*2];
__device__ int   g_gstart[Gg+1];
__device__ float g_cat[Gg*256];
__device__ float g_hd[Gg*128];
__device__ float g_logits[Gg*COUT];

// ---------------- small utility kernels ----------------
__global__ void fill_f32(float* p, float v, int n) {
    int i = blockIdx.x*blockDim.x + threadIdx.x;
    if (i < n) p[i] = v;
}

__global__ void count_deg(const int* __restrict__ src, float* deg, int E) {
    int i = blockIdx.x*blockDim.x + threadIdx.x;
    if (i < E) atomicAdd(&deg[src[i]], 1.0f);
}

__global__ void rsqrt_inplace(float* p, int n) {
    int i = blockIdx.x*blockDim.x + threadIdx.x;
    if (i < n) p[i] = rsqrtf(p[i]);
}

__global__ void gstart_kernel(const int* __restrict__ batch, int* gstart, int n, int G) {
    int i = blockIdx.x*blockDim.x + threadIdx.x;
    if (i >= n) return;
    int b  = batch[i];
    int pb = (i == 0) ? -1 : batch[i-1];
    for (int g = pb+1; g <= b; g++) gstart[g] = i;
    if (i == n-1) {
        for (int g = b+1; g <= G; g++) gstart[g] = n;
    }
}

// column sums & sumsq. stride (grid*block) is a multiple of C -> column fixed per thread.
template<int C>
__global__ void colstats(const float* __restrict__ A, int lda, int aoff,
                         const float* __restrict__ rs, int rss, int rso,
                         int n, float* sums) {
    long total  = (long)n * C;
    long stride = (long)gridDim.x * blockDim.x;
    long i0     = (long)blockIdx.x*blockDim.x + threadIdx.x;
    if (i0 >= total) return;
    int c = (int)(i0 % C);
    float s0 = 0.f, s1 = 0.f;
    for (long i = i0; i < total; i += stride) {
        int r = (int)(i / C);
        float v = A[(long)r*lda + aoff + c];
        if (rs) v *= rs[r*rss + rso];
        s0 += v; s1 += v*v;
    }
    atomicAdd(&sums[c], s0);
    atomicAdd(&sums[C+c], s1);
}

__global__ void finalize_stats(const float* __restrict__ sums, int C, float inv_n,
                               float* mean, float* rstd) {
    int c = threadIdx.x + blockIdx.x*blockDim.x;
    if (c < C) {
        float m = sums[c]*inv_n;
        float var = sums[C+c]*inv_n - m*m;
        mean[c] = m;
        rstd[c] = rsqrtf(var + EPSBN);
    }
}

// ---------------- big GEMM v2 ----------------
// out[n,128] = act( BN(rs*A)[n,128] @ W[128,128] )
// optional fused self-loop init: sout[r,:] = out[r,:] * dis[r]^2
// 128 rows per block, whole K=128 resident, 256 threads, 8x8 per thread.
static constexpr int GEMM_SMEM = 2 * 128 * 128 * 4;   // As + Ws

__global__ __launch_bounds__(256) void gemm128(
    const float* __restrict__ A,
    const float* __restrict__ rs, int rss, int rso,
    const float* __restrict__ mean, const float* __restrict__ rstd,
    const float* __restrict__ W,
    float* __restrict__ out,
    float* __restrict__ sout, const float* __restrict__ dis,
    int n, int act)
{
    extern __shared__ float sm[];
    float* As = sm;               // [128][128] row-major (row, k)
    float* Ws = sm + 128*128;     // [128][128] row-major (k, col)
    int tid  = threadIdx.x;
    int row0 = blockIdx.x * 128;

    // load W
    const float4* Wg = (const float4*)W;
    float4* Ws4 = (float4*)Ws;
    #pragma unroll 4
    for (int i = tid; i < 128*32; i += 256) Ws4[i] = Wg[i];

    // load A tile with fused row-scale + BN
    for (int i = tid; i < 128*32; i += 256) {
        int r = i >> 5, cq = i & 31;
        int gr = row0 + r;
        float4 v = make_float4(0.f,0.f,0.f,0.f);
        if (gr < n) {
            v = ((const float4*)A)[gr*32 + cq];
            float sc = rs ? rs[gr*rss + rso] : 1.f;
            int c = cq*4;
            v.x = (v.x*sc - mean[c+0])*rstd[c+0] + BNB;
            v.y = (v.y*sc - mean[c+1])*rstd[c+1] + BNB;
            v.z = (v.z*sc - mean[c+2])*rstd[c+2] + BNB;
            v.w = (v.w*sc - mean[c+3])*rstd[c+3] + BNB;
        }
        ((float4*)As)[i] = v;
    }
    __syncthreads();

    int tc = tid & 15, tr = tid >> 4;
    int r0 = tr*4, r1 = 64 + tr*4;
    int c0 = tc*4, c1 = 64 + tc*4;

    float acc[8][8];
    #pragma unroll
    for (int i = 0; i < 8; i++)
        #pragma unroll
        for (int j = 0; j < 8; j++) acc[i][j] = 0.f;

    for (int k = 0; k < 128; k += 4) {
        float4 a4[8];
        #pragma unroll
        for (int i = 0; i < 4; i++) {
            a4[i]   = *(const float4*)&As[(r0+i)*128 + k];
            a4[4+i] = *(const float4*)&As[(r1+i)*128 + k];
        }
        #pragma unroll
        for (int kk = 0; kk < 4; kk++) {
            float4 w0 = *(const float4*)&Ws[(k+kk)*128 + c0];
            float4 w1 = *(const float4*)&Ws[(k+kk)*128 + c1];
            float wv[8] = {w0.x,w0.y,w0.z,w0.w, w1.x,w1.y,w1.z,w1.w};
            #pragma unroll
            for (int i = 0; i < 8; i++) {
                float a = ((const float*)&a4[i])[kk];
                #pragma unroll
                for (int j = 0; j < 8; j++) acc[i][j] += a * wv[j];
            }
        }
    }

    float4* O4 = (float4*)out;
    float4* S4 = (float4*)sout;
    #pragma unroll
    for (int i = 0; i < 8; i++) {
        int gr = row0 + ((i < 4) ? (r0 + i) : (r1 + i - 4));
        if (gr < n) {
            float4 o0, o1;
            o0.x=acc[i][0]; o0.y=acc[i][1]; o0.z=acc[i][2]; o0.w=acc[i][3];
            o1.x=acc[i][4]; o1.y=acc[i][5]; o1.z=acc[i][6]; o1.w=acc[i][7];
            if (act == 1) {
                o0.x=fmaxf(o0.x,0.f); o0.y=fmaxf(o0.y,0.f);
                o0.z=fmaxf(o0.z,0.f); o0.w=fmaxf(o0.w,0.f);
                o1.x=fmaxf(o1.x,0.f); o1.y=fmaxf(o1.y,0.f);
                o1.z=fmaxf(o1.z,0.f); o1.w=fmaxf(o1.w,0.f);
            }
            O4[gr*32 + tc]      = o0;
            O4[gr*32 + 16 + tc] = o1;
            if (sout) {
                float d = dis[gr]; float d2 = d*d;
                float4 s0, s1;
                s0.x=o0.x*d2; s0.y=o0.y*d2; s0.z=o0.z*d2; s0.w=o0.w*d2;
                s1.x=o1.x*d2; s1.y=o1.y*d2; s1.z=o1.z*d2; s1.w=o1.w*d2;
                S4[gr*32 + tc]      = s0;
                S4[gr*32 + 16 + tc] = s1;
            }
        }
    }
}

// ---------------- scatter kernels ----------------
// one warp per edge: s[dst] += dis[src]*ew*dis[dst] * t[src]  (vector red)
__global__ __launch_bounds__(256) void scatter128(
    const float* __restrict__ t, const int* __restrict__ src, const int* __restrict__ dst,
    const float* __restrict__ dis, const float* __restrict__ ew, int ewo,
    float* __restrict__ s_out, int E) {
    int gtid = blockIdx.x*blockDim.x + threadIdx.x;
    int e = gtid >> 5, lane = gtid & 31;
    if (e >= E) return;
    int sv = src[e], dv = dst[e];
    float w = dis[sv]*dis[dv];
    if (ew) w *= ew[e*2 + ewo];
    float4 v = ((const float4*)t)[sv*32 + lane];
    float* o = s_out + dv*128 + lane*4;
    asm volatile("red.global.add.v4.f32 [%0], {%1, %2, %3, %4};"
                 :: "l"(o), "f"(w*v.x), "f"(w*v.y), "f"(w*v.z), "f"(w*v.w)
                 : "memory");
}

__global__ void bias_relu(const float* __restrict__ s, const float* __restrict__ b,
                          float* __restrict__ h, int n) {
    int i = blockIdx.x*blockDim.x + threadIdx.x;
    if (i >= n*32) return;
    float4 x = ((const float4*)s)[i];
    float4 bb = ((const float4*)b)[i & 31];
    float4 o;
    o.x = fmaxf(x.x + bb.x, 0.f); o.y = fmaxf(x.y + bb.y, 0.f);
    o.z = fmaxf(x.z + bb.z, 0.f); o.w = fmaxf(x.w + bb.w, 0.f);
    ((float4*)h)[i] = o;
}

// ---------------- attention ----------------
__global__ void proj_kernel(const float* __restrict__ h, const float* __restrict__ eW,
                            const float* __restrict__ naW, float* __restrict__ epro,
                            float* __restrict__ t2, int n) {
    __shared__ float sEW[512];
    __shared__ float sNA[256];
    int tid = threadIdx.x;
    for (int i = tid; i < 512; i += blockDim.x) sEW[i] = eW[i];
    for (int i = tid; i < 256; i += blockDim.x) sNA[i] = naW[i];
    __syncthreads();
    int lane = tid & 31;
    int w0 = (blockIdx.x*blockDim.x + tid) >> 5;
    int nw = (gridDim.x*blockDim.x) >> 5;
    for (int v = w0; v < n; v += nw) {
        float4 hv = ((const float4*)h)[v*32 + lane];
        float hx[4] = {hv.x, hv.y, hv.z, hv.w};
        float p0=0,p1=0,q0=0,q1=0,u0=0,u1=0;
        #pragma unroll
        for (int i = 0; i < 4; i++) {
            int k = lane*4 + i; float x = hx[i];
            p0 += x*sEW[k*2+0];        p1 += x*sEW[k*2+1];
            q0 += x*sEW[(128+k)*2+0];  q1 += x*sEW[(128+k)*2+1];
            u0 += x*sNA[k*2+0];        u1 += x*sNA[k*2+1];
        }
        #pragma unroll
        for (int o = 16; o; o >>= 1) {
            p0 += __shfl_xor_sync(0xffffffffu, p0, o);
            p1 += __shfl_xor_sync(0xffffffffu, p1, o);
            q0 += __shfl_xor_sync(0xffffffffu, q0, o);
            q1 += __shfl_xor_sync(0xffffffffu, q1, o);
            u0 += __shfl_xor_sync(0xffffffffu, u0, o);
            u1 += __shfl_xor_sync(0xffffffffu, u1, o);
        }
        if (lane == 0) {
            epro[v*4+0]=p0; epro[v*4+1]=p1; epro[v*4+2]=q0; epro[v*4+3]=q1;
            t2[v*2+0]=u0; t2[v*2+1]=u1;
        }
    }
}

__global__ void edge_att_kernel(const int* __restrict__ src, const int* __restrict__ dst,
                                const float* __restrict__ epro, const float* __restrict__ eb,
                                float* __restrict__ eatt, float* deg0, float* deg1, int E) {
    int e = blockIdx.x*blockDim.x + threadIdx.x;
    if (e >= E) return;
    int s = src[e], d = dst[e];
    float l0 = epro[s*4+0] + epro[d*4+2] + eb[0];
    float l1 = epro[s*4+1] + epro[d*4+3] + eb[1];
    float m = fmaxf(l0, l1);
    float e0 = expf(l0 - m), e1 = expf(l1 - m);
    float inv = 1.f/(e0+e1);
    float a0 = e0*inv, a1 = e1*inv;
    eatt[e*2+0] = a0; eatt[e*2+1] = a1;
    atomicAdd(&deg0[s], a0);
    atomicAdd(&deg1[s], a1);
}

__global__ void natt_init(const float* __restrict__ t2, const float* __restrict__ disU,
                          float* __restrict__ nraw, int n) {
    int v = blockIdx.x*blockDim.x + threadIdx.x;
    if (v >= n) return;
    float d = disU[v]; d *= d;
    nraw[v*2+0] = t2[v*2+0]*d;
    nraw[v*2+1] = t2[v*2+1]*d;
}

__global__ void scatter2(const int* __restrict__ src, const int* __restrict__ dst,
                         const float* __restrict__ disU, const float* __restrict__ t2,
                         float* __restrict__ nraw, int E) {
    int e = blockIdx.x*blockDim.x + threadIdx.x;
    if (e >= E) return;
    int s = src[e], d = dst[e];
    float c = disU[s]*disU[d];
    float* o = &nraw[d*2];
    asm volatile("red.global.add.v2.f32 [%0], {%1, %2};"
                 :: "l"(o), "f"(c*t2[s*2+0]), "f"(c*t2[s*2+1]) : "memory");
}

__global__ void natt_fin(const float* __restrict__ nraw, const float* __restrict__ nab,
                         float* __restrict__ natt, int n) {
    int v = blockIdx.x*blockDim.x + threadIdx.x;
    if (v >= n) return;
    float l0 = nraw[v*2+0] + nab[0];
    float l1 = nraw[v*2+1] + nab[1];
    float m = fmaxf(l0, l1);
    float e0 = expf(l0 - m), e1 = expf(l1 - m);
    float inv = 1.f/(e0+e1);
    natt[v*2+0] = e0*inv; natt[v*2+1] = e1*inv;
}

// pool with fused bias + elu
__global__ void pool_elu(const float* __restrict__ s, const float* __restrict__ b,
                         const int* __restrict__ gstart, float* __restrict__ cat, int off) {
    int g = blockIdx.x, c = threadIdx.x;
    int st = gstart[g], en = gstart[g+1];
    float bc = b[c], acc = 0.f;
    for (int v = st; v < en; v++) {
        float z = s[v*128 + c] + bc;
        acc += (z > 0.f) ? z : expm1f(z);
    }
    cat[g*256 + off + c] = acc;
}

// ---------------- head GEMM: one block per row ----------------
__global__ void head_gemm(const float* __restrict__ A, int lda, int aoff,
                          const float* __restrict__ mean, const float* __restrict__ rstd,
                          const float* __restrict__ W, const float* __restrict__ b,
                          float* __restrict__ out, int K, int cols, int act) {
    __shared__ float a[256];
    int r = blockIdx.x;
    for (int k = threadIdx.x; k < K; k += blockDim.x)
        a[k] = (A[r*lda + aoff + k] - mean[k]) * rstd[k] + BNB;
    __syncthreads();
    for (int c = threadIdx.x; c < cols; c += blockDim.x) {
        float acc = b[c];
        for (int k = 0; k < K; k++) acc += a[k] * W[k*cols + c];
        if (act == 1) acc = fmaxf(acc, 0.f);
        else if (act == 2) {
            acc = (acc > 0.f) ? acc : expm1f(acc);
            acc = (acc > 0.f) ? acc : expm1f(acc);
        }
        out[r*cols + c] = acc;
    }
}

__global__ void log_softmax10(const float* __restrict__ in, float* __restrict__ out, int G) {
    int r = blockIdx.x*blockDim.x + threadIdx.x;
    if (r >= G) return;
    float v[COUT]; float m = -1e30f;
    #pragma unroll
    for (int i = 0; i < COUT; i++) { v[i] = in[r*COUT + i]; m = fmaxf(m, v[i]); }
    float s = 0.f;
    #pragma unroll
    for (int i = 0; i < COUT; i++) s += expf(v[i] - m);
    float lse = m + logf(s);
    #pragma unroll
    for (int i = 0; i < COUT; i++) out[r*COUT + i] = v[i] - lse;
}

// ---------------- host orchestration ----------------
extern "C" void kernel_launch(void* const* d_in, const int* in_sizes, int n_in,
                              void* d_out, int out_size) {
    const float* x      = (const float*)d_in[0];
    const float* W_feat = (const float*)d_in[1];
    const float* conv_Ws= (const float*)d_in[2];
    const float* conv_bs= (const float*)d_in[3];
    const float* eW     = (const float*)d_in[4];
    const float* eb     = (const float*)d_in[5];
    const float* naW    = (const float*)d_in[6];
    const float* nab    = (const float*)d_in[7];
    const float* xcW    = (const float*)d_in[8];
    const float* xcb    = (const float*)d_in[9];
    const float* xoW    = (const float*)d_in[10];
    const float* xob    = (const float*)d_in[11];
    const float* cW1    = (const float*)d_in[12];
    const float* cb1    = (const float*)d_in[13];
    const float* cW2    = (const float*)d_in[14];
    const float* cb2    = (const float*)d_in[15];
    const float* oW1    = (const float*)d_in[16];
    const float* ob1    = (const float*)d_in[17];
    const float* oW2    = (const float*)d_in[18];
    const float* ob2    = (const float*)d_in[19];
    const float* coW1   = (const float*)d_in[20];
    const float* cob1   = (const float*)d_in[21];
    const float* coW2   = (const float*)d_in[22];
    const float* cob2   = (const float*)d_in[23];
    const int* esrc     = (const int*)d_in[24];
    const int* edst     = (const int*)d_in[25];
    const int* batch    = (const int*)d_in[26];
    float* out = (float*)d_out;

    float *p_h,*p_t,*p_s,*p_stats,*p_mean,*p_rstd,*p_disU,*p_dis0,*p_dis1;
    float *p_epro,*p_t2,*p_nraw,*p_natt,*p_eatt,*p_cat,*p_hd,*p_logits;
    int* p_gstart;
    cudaGetSymbolAddress((void**)&p_h, g_h);
    cudaGetSymbolAddress((void**)&p_t, g_t);
    cudaGetSymbolAddress((void**)&p_s, g_s);
    cudaGetSymbolAddress((void**)&p_stats, g_stats);
    cudaGetSymbolAddress((void**)&p_mean, g_mean);
    cudaGetSymbolAddress((void**)&p_rstd, g_rstd);
    cudaGetSymbolAddress((void**)&p_disU, g_disU);
    cudaGetSymbolAddress((void**)&p_dis0, g_dis0);
    cudaGetSymbolAddress((void**)&p_dis1, g_dis1);
    cudaGetSymbolAddress((void**)&p_epro, g_epro);
    cudaGetSymbolAddress((void**)&p_t2, g_t2);
    cudaGetSymbolAddress((void**)&p_nraw, g_nraw);
    cudaGetSymbolAddress((void**)&p_natt, g_natt);
    cudaGetSymbolAddress((void**)&p_eatt, g_eatt);
    cudaGetSymbolAddress((void**)&p_cat, g_cat);
    cudaGetSymbolAddress((void**)&p_hd, g_hd);
    cudaGetSymbolAddress((void**)&p_logits, g_logits);
    cudaGetSymbolAddress((void**)&p_gstart, g_gstart);

    cudaFuncSetAttribute(gemm128, cudaFuncAttributeMaxDynamicSharedMemorySize, GEMM_SMEM);

    const int N = Nn, E = Ee, G = Gg;
    const int NB = (N + 127) / 128;
    const int NT = (N + 255) / 256;
    const int ET = (E + 255) / 256;
    const int NV = (N*32 + 255) / 256;
    const int SCAT = (E*32) / 256;

    // degrees (unit) + group starts
    fill_f32<<<NT,256>>>(p_disU, 1.f, N);
    fill_f32<<<NT,256>>>(p_dis0, 1.f, N);
    fill_f32<<<NT,256>>>(p_dis1, 1.f, N);
    count_deg<<<ET,256>>>(esrc, p_disU, E);
    rsqrt_inplace<<<NT,256>>>(p_disU, N);
    gstart_kernel<<<NT,256>>>(batch, p_gstart, N, G);

    // h = relu(BN(x) @ W_feat)
    cudaMemsetAsync(p_stats, 0, 2048);
    colstats<128><<<512,256>>>(x, 128, 0, nullptr, 0, 0, N, p_stats);
    finalize_stats<<<1,256>>>(p_stats, 128, 1.f/N, p_mean, p_rstd);
    gemm128<<<NB,256,GEMM_SMEM>>>(x, nullptr,0,0, p_mean, p_rstd, W_feat,
                                  p_h, nullptr, nullptr, N, 1);

    // 3 GCN layers
    for (int l = 0; l < 3; l++) {
        cudaMemsetAsync(p_stats, 0, 2048);
        colstats<128><<<512,256>>>(p_h, 128, 0, nullptr, 0, 0, N, p_stats);
        finalize_stats<<<1,256>>>(p_stats, 128, 1.f/N, p_mean, p_rstd);
        gemm128<<<NB,256,GEMM_SMEM>>>(p_h, nullptr,0,0, p_mean, p_rstd,
                                      conv_Ws + l*128*128, p_t, p_s, p_disU, N, 0);
        scatter128<<<SCAT,256>>>(p_t, esrc, edst, p_disU, nullptr, 0, p_s, E);
        bias_relu<<<NV,256>>>(p_s, conv_bs + l*128, p_h, N);
    }

    // attention projections + edge/node attention
    proj_kernel<<<512,256>>>(p_h, eW, naW, p_epro, p_t2, N);
    edge_att_kernel<<<ET,256>>>(esrc, edst, p_epro, eb, p_eatt, p_dis0, p_dis1, E);
    rsqrt_inplace<<<NT,256>>>(p_dis0, N);
    rsqrt_inplace<<<NT,256>>>(p_dis1, N);
    natt_init<<<NT,256>>>(p_t2, p_disU, p_nraw, N);
    scatter2<<<ET,256>>>(esrc, edst, p_disU, p_t2, p_nraw, E);
    natt_fin<<<NT,256>>>(p_nraw, nab, p_natt, N);

    // XC branch
    cudaMemsetAsync(p_stats, 0, 2048);
    colstats<128><<<512,256>>>(p_h, 128, 0, p_natt, 2, 0, N, p_stats);
    finalize_stats<<<1,256>>>(p_stats, 128, 1.f/N, p_mean, p_rstd);
    gemm128<<<NB,256,GEMM_SMEM>>>(p_h, p_natt, 2, 0, p_mean, p_rstd, xcW,
                                  p_t, p_s, p_dis0, N, 0);
    scatter128<<<SCAT,256>>>(p_t, esrc, edst, p_dis0, p_eatt, 0, p_s, E);
    pool_elu<<<G,128>>>(p_s, xcb, p_gstart, p_cat, 0);

    // XO branch
    cudaMemsetAsync(p_stats, 0, 2048);
    colstats<128><<<512,256>>>(p_h, 128, 0, p_natt, 2, 1, N, p_stats);
    finalize_stats<<<1,256>>>(p_stats, 128, 1.f/N, p_mean, p_rstd);
    gemm128<<<NB,256,GEMM_SMEM>>>(p_h, p_natt, 2, 1, p_mean, p_rstd, xoW,
                                  p_t, p_s, p_dis1, N, 0);
    scatter128<<<SCAT,256>>>(p_t, esrc, edst, p_dis1, p_eatt, 1, p_s, E);
    pool_elu<<<G,128>>>(p_s, xob, p_gstart, p_cat, 128);

    // ---- C head ----
    cudaMemsetAsync(p_stats, 0, 2048);
    colstats<128><<<64,256>>>(p_cat, 256, 0, nullptr, 0, 0, G, p_stats);
    finalize_stats<<<1,256>>>(p_stats, 128, 1.f/G, p_mean, p_rstd);
    head_gemm<<<G,128>>>(p_cat, 256, 0, p_mean, p_rstd, cW1, cb1, p_hd, 128, 128, 1);
    cudaMemsetAsync(p_stats, 0, 2048);
    colstats<128><<<64,256>>>(p_hd, 128, 0, nullptr, 0, 0, G, p_stats);
    finalize_stats<<<1,256>>>(p_stats, 128, 1.f/G, p_mean, p_rstd);
    head_gemm<<<G,128>>>(p_hd, 128, 0, p_mean, p_rstd, cW2, cb2, p_logits, 128, COUT, 0);
    log_softmax10<<<(G+127)/128,128>>>(p_logits, out, G);

    // ---- O head ----
    cudaMemsetAsync(p_stats, 0, 2048);
    colstats<128><<<64,256>>>(p_cat, 256, 128, nullptr, 0, 0, G, p_stats);
    finalize_stats<<<1,256>>>(p_stats, 128, 1.f/G, p_mean, p_rstd);
    head_gemm<<<G,128>>>(p_cat, 256, 128, p_mean, p_rstd, oW1, ob1, p_hd, 128, 128, 1);
    cudaMemsetAsync(p_stats, 0, 2048);
    colstats<128><<<64,256>>>(p_hd, 128, 0, nullptr, 0, 0, G, p_stats);
    finalize_stats<<<1,256>>>(p_stats, 128, 1.f/G, p_mean, p_rstd);
    head_gemm<<<G,128>>>(p_hd, 128, 0, p_mean, p_rstd, oW2, ob2, p_logits, 128, COUT, 0);
    log_softmax10<<<(G+127)/128,128>>>(p_logits, out + G*COUT, G);

    // ---- CO head ----
    cudaMemsetAsync(p_stats, 0, 2048);
    colstats<256><<<64,256>>>(p_cat, 256, 0, nullptr, 0, 0, G, p_stats);
    finalize_stats<<<1,256>>>(p_stats, 256, 1.f/G, p_mean, p_rstd);
    head_gemm<<<G,128>>>(p_cat, 256, 0, p_mean, p_rstd, coW1, cob1, p_hd, 256, 128, 2);
    cudaMemsetAsync(p_stats, 0, 2048);
    colstats<128><<<64,256>>>(p_hd, 128, 0, nullptr, 0, 0, G, p_stats);
    finalize_stats<<<1,256>>>(p_stats, 128, 1.f/G, p_mean, p_rstd);
    head_gemm<<<G,128>>>(p_hd, 128, 0, p_mean, p_rstd, coW2, cob2, p_logits, 128, COUT, 0);
    log_softmax10<<<(G+127)/128,128>>>(p_logits, out + 2*G*COUT, G);
}

// round 3
// speedup vs baseline: 1.5424x; 1.1912x over previous
#include <cuda_runtime.h>
#include <math.h>

#define Nn 50000
#define Ee 400000
#define Hh 128
#define Gg 512
#define COUT 10

static constexpr float EPSBN = 1e-5f;
static constexpr float BNB   = 1e-4f;

// ---------------- scratch (static device allocations) ----------------
__device__ float g_h[Nn*Hh];
__device__ float g_t[Nn*Hh];
__device__ float g_s[Nn*Hh];
__device__ float g_stats[512];
__device__ float g_mean[256];
__device__ float g_rstd[256];
__device__ float g_disU[Nn];
__device__ float g_dis0[Nn];
__device__ float g_dis1[Nn];
__device__ float g_epro[Nn*4];
__device__ float g_t2[Nn*2];
__device__ float g_natt[Nn*2];
__device__ float g_eatt[Ee*2];
__device__ int   g_gstart[Gg+1];
__device__ float g_cat[Gg*256];
__device__ float g_hd[Gg*128];
__device__ float g_logits[Gg*COUT];
// CSR by destination
__device__ int g_cnt[Nn];
__device__ int g_incl[Nn];
__device__ int g_bsum[64];
__device__ int g_rowptr[Nn+1];
__device__ int g_cursor[Nn];
__device__ int g_eid[Ee];

// ---------------- small utility kernels ----------------
__global__ void fill_f32(float* p, float v, int n) {
    int i = blockIdx.x*blockDim.x + threadIdx.x;
    if (i < n) p[i] = v;
}

__global__ void count_deg(const int* __restrict__ src, float* deg, int E) {
    int i = blockIdx.x*blockDim.x + threadIdx.x;
    if (i < E) atomicAdd(&deg[src[i]], 1.0f);
}

__global__ void rsqrt_inplace(float* p, int n) {
    int i = blockIdx.x*blockDim.x + threadIdx.x;
    if (i < n) p[i] = rsqrtf(p[i]);
}

__global__ void gstart_kernel(const int* __restrict__ batch, int* gstart, int n, int G) {
    int i = blockIdx.x*blockDim.x + threadIdx.x;
    if (i >= n) return;
    int b  = batch[i];
    int pb = (i == 0) ? -1 : batch[i-1];
    for (int g = pb+1; g <= b; g++) gstart[g] = i;
    if (i == n-1) {
        for (int g = b+1; g <= G; g++) gstart[g] = n;
    }
}

// ---------------- CSR build (sort edges by dst) ----------------
__global__ void hist_dst(const int* __restrict__ dst, int* cnt, int E) {
    int e = blockIdx.x*blockDim.x + threadIdx.x;
    if (e < E) atomicAdd(&cnt[dst[e]], 1);
}

__global__ void scan_block(const int* __restrict__ cnt, int* incl, int* bsum, int n) {
    __shared__ int sm[1024];
    int i = blockIdx.x*1024 + threadIdx.x;
    sm[threadIdx.x] = (i < n) ? cnt[i] : 0;
    __syncthreads();
    for (int off = 1; off < 1024; off <<= 1) {
        int t = (threadIdx.x >= off) ? sm[threadIdx.x - off] : 0;
        __syncthreads();
        sm[threadIdx.x] += t;
        __syncthreads();
    }
    if (i < n) incl[i] = sm[threadIdx.x];
    if (threadIdx.x == 1023) bsum[blockIdx.x] = sm[1023];
}

__global__ void scan_tops(int* bsum, int nb) {
    if (threadIdx.x == 0 && blockIdx.x == 0) {
        int s = 0;
        for (int i = 0; i < nb; i++) { s += bsum[i]; bsum[i] = s; }
    }
}

__global__ void make_rowptr(const int* __restrict__ cnt, const int* __restrict__ incl,
                            const int* __restrict__ bsum,
                            int* rowptr, int* cursor, int n, int E) {
    int i = blockIdx.x*blockDim.x + threadIdx.x;
    if (i < n) {
        int b = i >> 10;
        int ex = incl[i] - cnt[i] + ((b > 0) ? bsum[b-1] : 0);
        rowptr[i] = ex;
        cursor[i] = ex;
    }
    if (i == 0) rowptr[n] = E;
}

__global__ void fill_csr(const int* __restrict__ dst, int* cursor, int* eid, int E) {
    int e = blockIdx.x*blockDim.x + threadIdx.x;
    if (e < E) {
        int p = atomicAdd(&cursor[dst[e]], 1);
        eid[p] = e;
    }
}

// ---------------- BatchNorm stats ----------------
template<int C>
__global__ void colstats(const float* __restrict__ A, int lda, int aoff,
                         int n, float* sums) {
    long total  = (long)n * C;
    long stride = (long)gridDim.x * blockDim.x;
    long i0     = (long)blockIdx.x*blockDim.x + threadIdx.x;
    if (i0 >= total) return;
    int c = (int)(i0 % C);
    float s0 = 0.f, s1 = 0.f;
    for (long i = i0; i < total; i += stride) {
        int r = (int)(i / C);
        float v = A[(long)r*lda + aoff + c];
        s0 += v; s1 += v*v;
    }
    atomicAdd(&sums[c], s0);
    atomicAdd(&sums[C+c], s1);
}

// both natt-scaled channels in one pass
__global__ void colstats2(const float* __restrict__ A, const float* __restrict__ natt,
                          int n, float* sums) {
    long total  = (long)n * 128;
    long stride = (long)gridDim.x * blockDim.x;
    long i0     = (long)blockIdx.x*blockDim.x + threadIdx.x;
    if (i0 >= total) return;
    int c = (int)(i0 % 128);
    float s00=0.f, s01=0.f, s10=0.f, s11=0.f;
    for (long i = i0; i < total; i += stride) {
        int r = (int)(i / 128);
        float v = A[(long)r*128 + c];
        float v0 = v * natt[r*2+0];
        float v1 = v * natt[r*2+1];
        s00 += v0; s01 += v0*v0;
        s10 += v1; s11 += v1*v1;
    }
    atomicAdd(&sums[c], s00);
    atomicAdd(&sums[128+c], s01);
    atomicAdd(&sums[256+c], s10);
    atomicAdd(&sums[384+c], s11);
}

__global__ void finalize_stats(const float* __restrict__ sums, int C, float inv_n,
                               float* mean, float* rstd) {
    int c = threadIdx.x + blockIdx.x*blockDim.x;
    if (c < C) {
        float m = sums[c]*inv_n;
        float var = sums[C+c]*inv_n - m*m;
        mean[c] = m;
        rstd[c] = rsqrtf(var + EPSBN);
    }
}

// ---------------- big GEMM ----------------
// out[n,128] = act( BN(rs*A)[n,128] @ W[128,128] )
static constexpr int GEMM_SMEM = 2 * 128 * 128 * 4;

__global__ __launch_bounds__(256) void gemm128(
    const float* __restrict__ A,
    const float* __restrict__ rs, int rss, int rso,
    const float* __restrict__ mean, const float* __restrict__ rstd,
    const float* __restrict__ W,
    float* __restrict__ out,
    int n, int act)
{
    extern __shared__ float sm[];
    float* As = sm;               // [128][128]
    float* Ws = sm + 128*128;     // [128][128]
    int tid  = threadIdx.x;
    int row0 = blockIdx.x * 128;

    const float4* Wg = (const float4*)W;
    float4* Ws4 = (float4*)Ws;
    #pragma unroll 4
    for (int i = tid; i < 128*32; i += 256) Ws4[i] = Wg[i];

    for (int i = tid; i < 128*32; i += 256) {
        int r = i >> 5, cq = i & 31;
        int gr = row0 + r;
        float4 v = make_float4(0.f,0.f,0.f,0.f);
        if (gr < n) {
            v = ((const float4*)A)[gr*32 + cq];
            float sc = rs ? rs[gr*rss + rso] : 1.f;
            int c = cq*4;
            v.x = (v.x*sc - mean[c+0])*rstd[c+0] + BNB;
            v.y = (v.y*sc - mean[c+1])*rstd[c+1] + BNB;
            v.z = (v.z*sc - mean[c+2])*rstd[c+2] + BNB;
            v.w = (v.w*sc - mean[c+3])*rstd[c+3] + BNB;
        }
        ((float4*)As)[i] = v;
    }
    __syncthreads();

    int tc = tid & 15, tr = tid >> 4;
    int r0 = tr*4, r1 = 64 + tr*4;
    int c0 = tc*4, c1 = 64 + tc*4;

    float acc[8][8];
    #pragma unroll
    for (int i = 0; i < 8; i++)
        #pragma unroll
        for (int j = 0; j < 8; j++) acc[i][j] = 0.f;

    for (int k = 0; k < 128; k += 4) {
        float4 a4[8];
        #pragma unroll
        for (int i = 0; i < 4; i++) {
            a4[i]   = *(const float4*)&As[(r0+i)*128 + k];
            a4[4+i] = *(const float4*)&As[(r1+i)*128 + k];
        }
        #pragma unroll
        for (int kk = 0; kk < 4; kk++) {
            float4 w0 = *(const float4*)&Ws[(k+kk)*128 + c0];
            float4 w1 = *(const float4*)&Ws[(k+kk)*128 + c1];
            float wv[8] = {w0.x,w0.y,w0.z,w0.w, w1.x,w1.y,w1.z,w1.w};
            #pragma unroll
            for (int i = 0; i < 8; i++) {
                float a = ((const float*)&a4[i])[kk];
                #pragma unroll
                for (int j = 0; j < 8; j++) acc[i][j] += a * wv[j];
            }
        }
    }

    float4* O4 = (float4*)out;
    #pragma unroll
    for (int i = 0; i < 8; i++) {
        int gr = row0 + ((i < 4) ? (r0 + i) : (r1 + i - 4));
        if (gr < n) {
            float4 o0, o1;
            o0.x=acc[i][0]; o0.y=acc[i][1]; o0.z=acc[i][2]; o0.w=acc[i][3];
            o1.x=acc[i][4]; o1.y=acc[i][5]; o1.z=acc[i][6]; o1.w=acc[i][7];
            if (act == 1) {
                o0.x=fmaxf(o0.x,0.f); o0.y=fmaxf(o0.y,0.f);
                o0.z=fmaxf(o0.z,0.f); o0.w=fmaxf(o0.w,0.f);
                o1.x=fmaxf(o1.x,0.f); o1.y=fmaxf(o1.y,0.f);
                o1.z=fmaxf(o1.z,0.f); o1.w=fmaxf(o1.w,0.f);
            }
            O4[gr*32 + tc]      = o0;
            O4[gr*32 + 16 + tc] = o1;
        }
    }
}

// ---------------- CSR gather conv: one warp per dst node ----------------
// out[v] = act( dis[v]^2 * t[v] + sum_in_edges dis[src]*ew*dis[v] * t[src] (+ bias) )
__global__ __launch_bounds__(256) void gather128(
    const float* __restrict__ t,
    const int* __restrict__ rowptr, const int* __restrict__ eid,
    const int* __restrict__ esrc, const float* __restrict__ dis,
    const float* __restrict__ eatt, int ewo,
    const float* __restrict__ bias,
    float* __restrict__ out, int n, int act)
{
    int gt = blockIdx.x*blockDim.x + threadIdx.x;
    int v = gt >> 5, lane = gt & 31;
    if (v >= n) return;
    float dv = dis[v];
    float4 acc = ((const float4*)t)[v*32 + lane];
    float d2 = dv*dv;
    acc.x *= d2; acc.y *= d2; acc.z *= d2; acc.w *= d2;
    int st = rowptr[v], en = rowptr[v+1];
    for (int p = st; p < en; p++) {
        int e = __ldg(&eid[p]);
        int s = __ldg(&esrc[e]);
        float w = __ldg(&dis[s]) * dv;
        if (eatt) w *= __ldg(&eatt[e*2 + ewo]);
        float4 x = ((const float4*)t)[s*32 + lane];
        acc.x += w*x.x; acc.y += w*x.y; acc.z += w*x.z; acc.w += w*x.w;
    }
    if (bias) {
        float4 b = ((const float4*)bias)[lane];
        acc.x += b.x; acc.y += b.y; acc.z += b.z; acc.w += b.w;
    }
    if (act == 1) {
        acc.x = fmaxf(acc.x, 0.f); acc.y = fmaxf(acc.y, 0.f);
        acc.z = fmaxf(acc.z, 0.f); acc.w = fmaxf(acc.w, 0.f);
    }
    ((float4*)out)[v*32 + lane] = acc;
}

// ---------------- attention ----------------
__global__ void proj_kernel(const float* __restrict__ h, const float* __restrict__ eW,
                            const float* __restrict__ naW, float* __restrict__ epro,
                            float* __restrict__ t2, int n) {
    __shared__ float sEW[512];
    __shared__ float sNA[256];
    int tid = threadIdx.x;
    for (int i = tid; i < 512; i += blockDim.x) sEW[i] = eW[i];
    for (int i = tid; i < 256; i += blockDim.x) sNA[i] = naW[i];
    __syncthreads();
    int lane = tid & 31;
    int w0 = (blockIdx.x*blockDim.x + tid) >> 5;
    int nw = (gridDim.x*blockDim.x) >> 5;
    for (int v = w0; v < n; v += nw) {
        float4 hv = ((const float4*)h)[v*32 + lane];
        float hx[4] = {hv.x, hv.y, hv.z, hv.w};
        float p0=0,p1=0,q0=0,q1=0,u0=0,u1=0;
        #pragma unroll
        for (int i = 0; i < 4; i++) {
            int k = lane*4 + i; float x = hx[i];
            p0 += x*sEW[k*2+0];        p1 += x*sEW[k*2+1];
            q0 += x*sEW[(128+k)*2+0];  q1 += x*sEW[(128+k)*2+1];
            u0 += x*sNA[k*2+0];        u1 += x*sNA[k*2+1];
        }
        #pragma unroll
        for (int o = 16; o; o >>= 1) {
            p0 += __shfl_xor_sync(0xffffffffu, p0, o);
            p1 += __shfl_xor_sync(0xffffffffu, p1, o);
            q0 += __shfl_xor_sync(0xffffffffu, q0, o);
            q1 += __shfl_xor_sync(0xffffffffu, q1, o);
            u0 += __shfl_xor_sync(0xffffffffu, u0, o);
            u1 += __shfl_xor_sync(0xffffffffu, u1, o);
        }
        if (lane == 0) {
            epro[v*4+0]=p0; epro[v*4+1]=p1; epro[v*4+2]=q0; epro[v*4+3]=q1;
            t2[v*2+0]=u0; t2[v*2+1]=u1;
        }
    }
}

__global__ void edge_att_kernel(const int* __restrict__ src, const int* __restrict__ dst,
                                const float* __restrict__ epro, const float* __restrict__ eb,
                                float* __restrict__ eatt, float* deg0, float* deg1, int E) {
    int e = blockIdx.x*blockDim.x + threadIdx.x;
    if (e >= E) return;
    int s = src[e], d = dst[e];
    float l0 = epro[s*4+0] + epro[d*4+2] + eb[0];
    float l1 = epro[s*4+1] + epro[d*4+3] + eb[1];
    float m = fmaxf(l0, l1);
    float e0 = expf(l0 - m), e1 = expf(l1 - m);
    float inv = 1.f/(e0+e1);
    float a0 = e0*inv, a1 = e1*inv;
    eatt[e*2+0] = a0; eatt[e*2+1] = a1;
    atomicAdd(&deg0[s], a0);
    atomicAdd(&deg1[s], a1);
}

// fused node-attention gather + softmax (CSR)
__global__ void natt_gather(const float* __restrict__ t2,
                            const int* __restrict__ rowptr, const int* __restrict__ eid,
                            const int* __restrict__ esrc, const float* __restrict__ disU,
                            const float* __restrict__ nab,
                            float* __restrict__ natt, int n) {
    int v = blockIdx.x*blockDim.x + threadIdx.x;
    if (v >= n) return;
    float dv = disU[v];
    float d2 = dv*dv;
    float a0 = t2[v*2+0]*d2, a1 = t2[v*2+1]*d2;
    int st = rowptr[v], en = rowptr[v+1];
    for (int p = st; p < en; p++) {
        int e = eid[p];
        int s = esrc[e];
        float w = disU[s]*dv;
        a0 += w*t2[s*2+0];
        a1 += w*t2[s*2+1];
    }
    a0 += nab[0]; a1 += nab[1];
    float m = fmaxf(a0, a1);
    float e0 = expf(a0 - m), e1 = expf(a1 - m);
    float inv = 1.f/(e0+e1);
    natt[v*2+0] = e0*inv; natt[v*2+1] = e1*inv;
}

// pool with fused bias + elu
__global__ void pool_elu(const float* __restrict__ s, const float* __restrict__ b,
                         const int* __restrict__ gstart, float* __restrict__ cat, int off) {
    int g = blockIdx.x, c = threadIdx.x;
    int st = gstart[g], en = gstart[g+1];
    float bc = b[c], acc = 0.f;
    for (int v = st; v < en; v++) {
        float z = s[v*128 + c] + bc;
        acc += (z > 0.f) ? z : expm1f(z);
    }
    cat[g*256 + off + c] = acc;
}

// ---------------- head GEMM: one block per row ----------------
__global__ void head_gemm(const float* __restrict__ A, int lda, int aoff,
                          const float* __restrict__ mean, const float* __restrict__ rstd,
                          const float* __restrict__ W, const float* __restrict__ b,
                          float* __restrict__ out, int K, int cols, int act) {
    __shared__ float a[256];
    int r = blockIdx.x;
    for (int k = threadIdx.x; k < K; k += blockDim.x)
        a[k] = (A[r*lda + aoff + k] - mean[k]) * rstd[k] + BNB;
    __syncthreads();
    for (int c = threadIdx.x; c < cols; c += blockDim.x) {
        float acc = b[c];
        for (int k = 0; k < K; k++) acc += a[k] * W[k*cols + c];
        if (act == 1) acc = fmaxf(acc, 0.f);
        else if (act == 2) {
            acc = (acc > 0.f) ? acc : expm1f(acc);
            acc = (acc > 0.f) ? acc : expm1f(acc);
        }
        out[r*cols + c] = acc;
    }
}

__global__ void log_softmax10(const float* __restrict__ in, float* __restrict__ out, int G) {
    int r = blockIdx.x*blockDim.x + threadIdx.x;
    if (r >= G) return;
    float v[COUT]; float m = -1e30f;
    #pragma unroll
    for (int i = 0; i < COUT; i++) { v[i] = in[r*COUT + i]; m = fmaxf(m, v[i]); }
    float s = 0.f;
    #pragma unroll
    for (int i = 0; i < COUT; i++) s += expf(v[i] - m);
    float lse = m + logf(s);
    #pragma unroll
    for (int i = 0; i < COUT; i++) out[r*COUT + i] = v[i] - lse;
}

// ---------------- host orchestration ----------------
extern "C" void kernel_launch(void* const* d_in, const int* in_sizes, int n_in,
                              void* d_out, int out_size) {
    const float* x      = (const float*)d_in[0];
    const float* W_feat = (const float*)d_in[1];
    const float* conv_Ws= (const float*)d_in[2];
    const float* conv_bs= (const float*)d_in[3];
    const float* eW     = (const float*)d_in[4];
    const float* eb     = (const float*)d_in[5];
    const float* naW    = (const float*)d_in[6];
    const float* nab    = (const float*)d_in[7];
    const float* xcW    = (const float*)d_in[8];
    const float* xcb    = (const float*)d_in[9];
    const float* xoW    = (const float*)d_in[10];
    const float* xob    = (const float*)d_in[11];
    const float* cW1    = (const float*)d_in[12];
    const float* cb1    = (const float*)d_in[13];
    const float* cW2    = (const float*)d_in[14];
    const float* cb2    = (const float*)d_in[15];
    const float* oW1    = (const float*)d_in[16];
    const float* ob1    = (const float*)d_in[17];
    const float* oW2    = (const float*)d_in[18];
    const float* ob2    = (const float*)d_in[19];
    const float* coW1   = (const float*)d_in[20];
    const float* cob1   = (const float*)d_in[21];
    const float* coW2   = (const float*)d_in[22];
    const float* cob2   = (const float*)d_in[23];
    const int* esrc     = (const int*)d_in[24];
    const int* edst     = (const int*)d_in[25];
    const int* batch    = (const int*)d_in[26];
    float* out = (float*)d_out;

    float *p_h,*p_t,*p_s,*p_stats,*p_mean,*p_rstd,*p_disU,*p_dis0,*p_dis1;
    float *p_epro,*p_t2,*p_natt,*p_eatt,*p_cat,*p_hd,*p_logits;
    int *p_gstart,*p_cnt,*p_incl,*p_bsum,*p_rowptr,*p_cursor,*p_eid;
    cudaGetSymbolAddress((void**)&p_h, g_h);
    cudaGetSymbolAddress((void**)&p_t, g_t);
    cudaGetSymbolAddress((void**)&p_s, g_s);
    cudaGetSymbolAddress((void**)&p_stats, g_stats);
    cudaGetSymbolAddress((void**)&p_mean, g_mean);
    cudaGetSymbolAddress((void**)&p_rstd, g_rstd);
    cudaGetSymbolAddress((void**)&p_disU, g_disU);
    cudaGetSymbolAddress((void**)&p_dis0, g_dis0);
    cudaGetSymbolAddress((void**)&p_dis1, g_dis1);
    cudaGetSymbolAddress((void**)&p_epro, g_epro);
    cudaGetSymbolAddress((void**)&p_t2, g_t2);
    cudaGetSymbolAddress((void**)&p_natt, g_natt);
    cudaGetSymbolAddress((void**)&p_eatt, g_eatt);
    cudaGetSymbolAddress((void**)&p_cat, g_cat);
    cudaGetSymbolAddress((void**)&p_hd, g_hd);
    cudaGetSymbolAddress((void**)&p_logits, g_logits);
    cudaGetSymbolAddress((void**)&p_gstart, g_gstart);
    cudaGetSymbolAddress((void**)&p_cnt, g_cnt);
    cudaGetSymbolAddress((void**)&p_incl, g_incl);
    cudaGetSymbolAddress((void**)&p_bsum, g_bsum);
    cudaGetSymbolAddress((void**)&p_rowptr, g_rowptr);
    cudaGetSymbolAddress((void**)&p_cursor, g_cursor);
    cudaGetSymbolAddress((void**)&p_eid, g_eid);

    cudaFuncSetAttribute(gemm128, cudaFuncAttributeMaxDynamicSharedMemorySize, GEMM_SMEM);

    const int N = Nn, E = Ee, G = Gg;
    const int NB = (N + 127) / 128;
    const int NT = (N + 255) / 256;
    const int ET = (E + 255) / 256;
    const int GW = (N*32 + 255) / 256;        // gather: warp per node
    const int NSCAN = (N + 1023) / 1024;      // 49

    // ---- CSR build + degrees + group starts ----
    cudaMemsetAsync(p_cnt, 0, Nn*sizeof(int));
    hist_dst<<<ET,256>>>(edst, p_cnt, E);
    scan_block<<<NSCAN,1024>>>(p_cnt, p_incl, p_bsum, N);
    scan_tops<<<1,32>>>(p_bsum, NSCAN);
    make_rowptr<<<NT,256>>>(p_cnt, p_incl, p_bsum, p_rowptr, p_cursor, N, E);
    fill_csr<<<ET,256>>>(edst, p_cursor, p_eid, E);

    fill_f32<<<NT,256>>>(p_disU, 1.f, N);
    fill_f32<<<NT,256>>>(p_dis0, 1.f, N);
    fill_f32<<<NT,256>>>(p_dis1, 1.f, N);
    count_deg<<<ET,256>>>(esrc, p_disU, E);
    rsqrt_inplace<<<NT,256>>>(p_disU, N);
    gstart_kernel<<<NT,256>>>(batch, p_gstart, N, G);

    // ---- h = relu(BN(x) @ W_feat) ----
    cudaMemsetAsync(p_stats, 0, 2048);
    colstats<128><<<512,256>>>(x, 128, 0, N, p_stats);
    finalize_stats<<<1,256>>>(p_stats, 128, 1.f/N, p_mean, p_rstd);
    gemm128<<<NB,256,GEMM_SMEM>>>(x, nullptr,0,0, p_mean, p_rstd, W_feat, p_h, N, 1);

    // ---- 3 GCN layers ----
    for (int l = 0; l < 3; l++) {
        cudaMemsetAsync(p_stats, 0, 2048);
        colstats<128><<<512,256>>>(p_h, 128, 0, N, p_stats);
        finalize_stats<<<1,256>>>(p_stats, 128, 1.f/N, p_mean, p_rstd);
        gemm128<<<NB,256,GEMM_SMEM>>>(p_h, nullptr,0,0, p_mean, p_rstd,
                                      conv_Ws + l*128*128, p_t, N, 0);
        gather128<<<GW,256>>>(p_t, p_rowptr, p_eid, esrc, p_disU, nullptr, 0,
                              conv_bs + l*128, p_h, N, 1);
    }

    // ---- attention ----
    proj_kernel<<<512,256>>>(p_h, eW, naW, p_epro, p_t2, N);
    edge_att_kernel<<<ET,256>>>(esrc, edst, p_epro, eb, p_eatt, p_dis0, p_dis1, E);
    rsqrt_inplace<<<NT,256>>>(p_dis0, N);
    rsqrt_inplace<<<NT,256>>>(p_dis1, N);
    natt_gather<<<NT,256>>>(p_t2, p_rowptr, p_eid, esrc, p_disU, nab, p_natt, N);

    // ---- XC / XO stats (one fused pass) ----
    cudaMemsetAsync(p_stats, 0, 2048);
    colstats2<<<512,256>>>(p_h, p_natt, N, p_stats);
    finalize_stats<<<1,256>>>(p_stats,       128, 1.f/N, p_mean,       p_rstd);
    finalize_stats<<<1,256>>>(p_stats + 256, 128, 1.f/N, p_mean + 128, p_rstd + 128);

    // ---- XC branch ----
    gemm128<<<NB,256,GEMM_SMEM>>>(p_h, p_natt, 2, 0, p_mean, p_rstd, xcW, p_t, N, 0);
    gather128<<<GW,256>>>(p_t, p_rowptr, p_eid, esrc, p_dis0, p_eatt, 0,
                          nullptr, p_s, N, 0);
    pool_elu<<<G,128>>>(p_s, xcb, p_gstart, p_cat, 0);

    // ---- XO branch ----
    gemm128<<<NB,256,GEMM_SMEM>>>(p_h, p_natt, 2, 1, p_mean + 128, p_rstd + 128,
                                  xoW, p_t, N, 0);
    gather128<<<GW,256>>>(p_t, p_rowptr, p_eid, esrc, p_dis1, p_eatt, 1,
                          nullptr, p_s, N, 0);
    pool_elu<<<G,128>>>(p_s, xob, p_gstart, p_cat, 128);

    // ---- C head ----
    cudaMemsetAsync(p_stats, 0, 2048);
    colstats<128><<<64,256>>>(p_cat, 256, 0, G, p_stats);
    finalize_stats<<<1,256>>>(p_stats, 128, 1.f/G, p_mean, p_rstd);
    head_gemm<<<G,128>>>(p_cat, 256, 0, p_mean, p_rstd, cW1, cb1, p_hd, 128, 128, 1);
    cudaMemsetAsync(p_stats, 0, 2048);
    colstats<128><<<64,256>>>(p_hd, 128, 0, G, p_stats);
    finalize_stats<<<1,256>>>(p_stats, 128, 1.f/G, p_mean, p_rstd);
    head_gemm<<<G,128>>>(p_hd, 128, 0, p_mean, p_rstd, cW2, cb2, p_logits, 128, COUT, 0);
    log_softmax10<<<(G+127)/128,128>>>(p_logits, out, G);

    // ---- O head ----
    cudaMemsetAsync(p_stats, 0, 2048);
    colstats<128><<<64,256>>>(p_cat, 256, 128, G, p_stats);
    finalize_stats<<<1,256>>>(p_stats, 128, 1.f/G, p_mean, p_rstd);
    head_gemm<<<G,128>>>(p_cat, 256, 128, p_mean, p_rstd, oW1, ob1, p_hd, 128, 128, 1);
    cudaMemsetAsync(p_stats, 0, 2048);
    colstats<128><<<64,256>>>(p_hd, 128, 0, G, p_stats);
    finalize_stats<<<1,256>>>(p_stats, 128, 1.f/G, p_mean, p_rstd);
    head_gemm<<<G,128>>>(p_hd, 128, 0, p_mean, p_rstd, oW2, ob2, p_logits, 128, COUT, 0);
    log_softmax10<<<(G+127)/128,128>>>(p_logits, out + G*COUT, G);

    // ---- CO head ----
    cudaMemsetAsync(p_stats, 0, 2048);
    colstats<256><<<64,256>>>(p_cat, 256, 0, G, p_stats);
    finalize_stats<<<1,256>>>(p_stats, 256, 1.f/G, p_mean, p_rstd);
    head_gemm<<<G,128>>>(p_cat, 256, 0, p_mean, p_rstd, coW1, cob1, p_hd, 256, 128, 2);
    cudaMemsetAsync(p_stats, 0, 2048);
    colstats<128><<<64,256>>>(p_hd, 128, 0, G, p_stats);
    finalize_stats<<<1,256>>>(p_stats, 128, 1.f/G, p_mean, p_rstd);
    head_gemm<<<G,128>>>(p_hd, 128, 0, p_mean, p_rstd, coW2, cob2, p_logits, 128, COUT, 0);
    log_softmax10<<<(G+127)/128,128>>>(p_logits, out + 2*G*COUT, G);
}